// round 1
// baseline (speedup 1.0000x reference)
#include <cuda_runtime.h>
#include <math.h>

// x: (16, 10, 512, 512) f32. out: (16, 8, 512, 512) f32.
// Per pixel: mag = sqrt(x[8]^2 + x[9]^2); k = argmax over x[0..7] (first max);
// out[c] = (c==k) ? mag : 0.
//
// Vectorized: one thread per float4 (4 consecutive pixels). Channel stride in
// float4 units is (512*512)/4 = 65536; batch stride is 10x that for input,
// 8x for output. All accesses are 16B coalesced.

#define VPB 65536            // float4 vectors per channel (512*512/4)
#define NBATCH 16
#define TOTAL_VEC (NBATCH * VPB)   // 1,048,576 threads

__global__ __launch_bounds__(256) void histogram_layer_kernel(
    const float4* __restrict__ x, float4* __restrict__ out)
{
    int i = blockIdx.x * blockDim.x + threadIdx.x;
    if (i >= TOTAL_VEC) return;

    int b = i >> 16;          // i / VPB
    int p = i & (VPB - 1);    // i % VPB

    const float4* in_base = x + (size_t)b * 10 * VPB + p;

    // Load all 8 cosine vectors first (front-batched MLP), then grads.
    float4 c[8];
#pragma unroll
    for (int k = 0; k < 8; k++) c[k] = in_base[(size_t)k * VPB];
    float4 g0 = in_base[(size_t)8 * VPB];
    float4 g1 = in_base[(size_t)9 * VPB];

    // Per-lane argmax (strict > keeps first/lowest index on ties, like jnp.argmax)
    float bx = c[0].x, by = c[0].y, bz = c[0].z, bw = c[0].w;
    int ix = 0, iy = 0, iz = 0, iw = 0;
#pragma unroll
    for (int k = 1; k < 8; k++) {
        if (c[k].x > bx) { bx = c[k].x; ix = k; }
        if (c[k].y > by) { by = c[k].y; iy = k; }
        if (c[k].z > bz) { bz = c[k].z; iz = k; }
        if (c[k].w > bw) { bw = c[k].w; iw = k; }
    }

    float mx = sqrtf(g0.x * g0.x + g1.x * g1.x);
    float my = sqrtf(g0.y * g0.y + g1.y * g1.y);
    float mz = sqrtf(g0.z * g0.z + g1.z * g1.z);
    float mw = sqrtf(g0.w * g0.w + g1.w * g1.w);

    float4* out_base = out + (size_t)b * 8 * VPB + p;
#pragma unroll
    for (int k = 0; k < 8; k++) {
        float4 o;
        o.x = (ix == k) ? mx : 0.0f;
        o.y = (iy == k) ? my : 0.0f;
        o.z = (iz == k) ? mz : 0.0f;
        o.w = (iw == k) ? mw : 0.0f;
        out_base[(size_t)k * VPB] = o;
    }
}

extern "C" void kernel_launch(void* const* d_in, const int* in_sizes, int n_in,
                              void* d_out, int out_size)
{
    const float4* x = (const float4*)d_in[0];
    float4* out = (float4*)d_out;
    int threads = 256;
    int blocks = (TOTAL_VEC + threads - 1) / threads;  // 4096
    histogram_layer_kernel<<<blocks, threads>>>(x, out);
}